// round 13
// baseline (speedup 1.0000x reference)
#include <cuda_runtime.h>

#define NN     50000
#define NPAD   50016
#define MM     800000
#define DDIM   128
#define EDIM   32
#define KIN    160          // D + E
#define NLAYERS 2

#define BM   64             // edges per CTA (edge kernel)
#define KB   16             // K-chunk (edge kernel)
#define GB   32             // nodes per CTA (gru kernel)
#define GKB  8              // K-chunk (gru kernel)

#define EDGE_SMEM ((BM*KIN + BM*256 + KB*256 + BM) * 4)
#define GRU_SMEM  ((GB*256 + GKB*512 + GB*512) * 4)

typedef unsigned long long u64;

// ---------------- device scratch (globals: allocation-free rule) -------------
__device__ float g_state[NPAD * DDIM];          // 25.6 MB
__device__ float g_accum[NPAD * DDIM];          // 25.6 MB
__device__ float g_Wg[NLAYERS * 256 * 512];     // packed GRU weights
__device__ float g_bg[NLAYERS * 512];           // packed GRU biases

// ---------------- f32x2 helpers ----------------------------------------------
__device__ __forceinline__ u64 pack2(float x, float y) {
    u64 r; asm("mov.b64 %0, {%1,%2};" : "=l"(r) : "f"(x), "f"(y)); return r;
}
__device__ __forceinline__ void fma2(u64& d, u64 a, u64 b) {
    asm("fma.rn.f32x2 %0, %1, %2, %0;" : "+l"(d) : "l"(a), "l"(b));
}
__device__ __forceinline__ float2 unpack2(u64 v) {
    float lo, hi; asm("mov.b64 {%0,%1}, %2;" : "=f"(lo), "=f"(hi) : "l"(v));
    return make_float2(lo, hi);
}
__device__ __forceinline__ float sigmoidf_(float x) {
    return __fdividef(1.f, 1.f + __expf(-x));
}
__device__ __forceinline__ float tanhf_(float x) {
    // 1 - 2/(e^{2x}+1); saturates correctly at +-inf
    return 1.f - __fdividef(2.f, __expf(2.f * x) + 1.f);
}

// ---------------- small utility kernels --------------------------------------
__global__ void copyin_kernel(const float* __restrict__ nf) {
    int i = blockIdx.x * blockDim.x + threadIdx.x;
    if (i < NN * DDIM / 4) ((float4*)g_state)[i] = ((const float4*)nf)[i];
}
__global__ void copyout_kernel(float* __restrict__ out) {
    int i = blockIdx.x * blockDim.x + threadIdx.x;
    if (i < NN * DDIM / 4) ((float4*)out)[i] = ((const float4*)g_state)[i];
}
__global__ void zero_accum_kernel() {
    int i = blockIdx.x * blockDim.x + threadIdx.x;
    if (i < NPAD * DDIM / 4) ((float4*)g_accum)[i] = make_float4(0.f, 0.f, 0.f, 0.f);
}
__global__ void relu_kernel() {
    int i = blockIdx.x * blockDim.x + threadIdx.x;
    if (i < NN * DDIM / 4) {
        float4 v = ((float4*)g_state)[i];
        v.x = fmaxf(v.x, 0.f); v.y = fmaxf(v.y, 0.f);
        v.z = fmaxf(v.z, 0.f); v.w = fmaxf(v.w, 0.f);
        ((float4*)g_state)[i] = v;
    }
}

// Pack GRU weights: Wg[l][k][c], k in [0,256) = [msg | h] rows,
// c sections: [0,128)=r (Wih+Whh), [128,256)=z, [256,384)=gin (Wih only),
// [384,512)=ghn (Whh only).
__global__ void prep_kernel(const float* __restrict__ Wih, const float* __restrict__ bih,
                            const float* __restrict__ Whh, const float* __restrict__ bhh) {
    int idx = blockIdx.x * blockDim.x + threadIdx.x;
    if (idx < NLAYERS * 256 * 512) {
        int l = idx / (256 * 512);
        int rr = idx % (256 * 512);
        int k = rr / 512;
        int c = rr % 512;
        const float* wih = Wih + l * 128 * 384;
        const float* whh = Whh + l * 128 * 384;
        float v;
        if (c < 256) {                       // r,z: original col = c
            v = (k < 128) ? wih[k * 384 + c] : whh[(k - 128) * 384 + c];
        } else if (c < 384) {                // gin: original col = c
            v = (k < 128) ? wih[k * 384 + c] : 0.f;
        } else {                             // ghn: original col = c-128
            v = (k < 128) ? 0.f : whh[(k - 128) * 384 + (c - 128)];
        }
        g_Wg[idx] = v;
    }
    if (idx < NLAYERS * 512) {
        int l = idx / 512, c = idx % 512;
        const float* bi = bih + l * 384;
        const float* bh = bhh + l * 384;
        float v;
        if (c < 256)      v = bi[c] + bh[c];
        else if (c < 384) v = bi[c];
        else              v = bh[c - 128];
        g_bg[idx] = v;
    }
}

// ---------------- fused edge kernel ------------------------------------------
// Per CTA: 64 edges. X[64,160] -> H[64,256]=relu(X@[W1|A1]+[b1|ab1])
// -> OUT[64,256]=[H1@W2 | H2@A2] -> msg*(sigmoid(att)) -> RED.ADD into g_accum.
__global__ void __launch_bounds__(256) edge_kernel(
    const int*   __restrict__ ei,  const float* __restrict__ ef,
    const float* __restrict__ W1l, const float* __restrict__ b1l,
    const float* __restrict__ W2l, const float* __restrict__ b2l,
    const float* __restrict__ A1l, const float* __restrict__ ab1l,
    const float* __restrict__ A2l, const float* __restrict__ ab2l)
{
    extern __shared__ float sm[];
    float* sX = sm;                       // 64 x 160
    float* sH = sX + BM * KIN;            // 64 x 256 (later reused as OUT)
    float* sW = sH + BM * 256;            // 16 x 256
    int*   sDst = (int*)(sW + KB * 256);  // 64

    const int tid  = threadIdx.x;
    const int e0   = blockIdx.x * BM;
    const int w    = tid >> 5;
    const int lane = tid & 31;

    // ---- gather X = [state[src]-state[dst] | edge_feat] ----
#pragma unroll
    for (int j = 0; j < 8; j++) {
        int m   = w * 8 + j;
        int src = __ldg(ei + e0 + m);
        int dst = __ldg(ei + MM + e0 + m);
        if (lane == 0) sDst[m] = dst;
        float4 s4 = *(const float4*)(g_state + src * DDIM + lane * 4);
        float4 d4 = *(const float4*)(g_state + dst * DDIM + lane * 4);
        float4 x  = make_float4(s4.x - d4.x, s4.y - d4.y, s4.z - d4.z, s4.w - d4.w);
        *(float4*)(sX + m * KIN + lane * 4) = x;
        if (lane < 8)
            *(float4*)(sX + m * KIN + 128 + lane * 4) =
                *(const float4*)(ef + (e0 + m) * EDIM + lane * 4);
    }

    const int trow = tid >> 5;     // 8 row groups x 8 rows
    const int tcol = tid & 31;     // 32 col groups x 8 cols
    const int c0   = tcol * 8;

    // ---- prefetch setup for GEMM1 weights [W1 | A1], rows = K ----
    const float* wp[4];
#pragma unroll
    for (int i = 0; i < 4; i++) {
        int u = tid + 256 * i;
        int r = u >> 6;
        int c = (u & 63) * 4;
        const float* base = (c < 128) ? (W1l + c) : (A1l + (c - 128));
        wp[i] = base + r * 128;
    }
    float4 pf[4];
#pragma unroll
    for (int i = 0; i < 4; i++) { pf[i] = __ldg((const float4*)wp[i]); wp[i] += KB * 128; }
#pragma unroll
    for (int i = 0; i < 4; i++) *(float4*)(sW + (tid + 256 * i) * 4) = pf[i];
    __syncthreads();

    u64 acc[8][4];
#pragma unroll
    for (int r = 0; r < 8; r++)
#pragma unroll
        for (int p = 0; p < 4; p++) acc[r][p] = 0ull;

    // ---- GEMM1: K = 160 (10 chunks of 16) ----
#pragma unroll 1
    for (int ch = 0; ch < 10; ch++) {
        if (ch < 9) {
#pragma unroll
            for (int i = 0; i < 4; i++) { pf[i] = __ldg((const float4*)wp[i]); wp[i] += KB * 128; }
        }
        const int kbase = ch * KB;
#pragma unroll
        for (int kq = 0; kq < 4; kq++) {
            float4 xr[8];
#pragma unroll
            for (int r = 0; r < 8; r++)
                xr[r] = *(const float4*)(sX + (trow * 8 + r) * KIN + kbase + kq * 4);
#pragma unroll
            for (int kk = 0; kk < 4; kk++) {
                const float* wr = sW + (kq * 4 + kk) * 256 + c0;
                ulonglong2 wa = *(const ulonglong2*)wr;
                ulonglong2 wb = *(const ulonglong2*)(wr + 4);
#pragma unroll
                for (int r = 0; r < 8; r++) {
                    float x = (kk == 0) ? xr[r].x : (kk == 1) ? xr[r].y : (kk == 2) ? xr[r].z : xr[r].w;
                    u64 xx = pack2(x, x);
                    fma2(acc[r][0], xx, wa.x);
                    fma2(acc[r][1], xx, wa.y);
                    fma2(acc[r][2], xx, wb.x);
                    fma2(acc[r][3], xx, wb.y);
                }
            }
        }
        __syncthreads();
        if (ch < 9) {
#pragma unroll
            for (int i = 0; i < 4; i++) *(float4*)(sW + (tid + 256 * i) * 4) = pf[i];
            __syncthreads();
        }
    }

    // ---- GEMM1 epilogue: bias + relu -> sH ----
    {
        const float* bp = (tcol < 16) ? (b1l + c0) : (ab1l + (c0 - 128));
        float4 blo = __ldg((const float4*)bp);
        float4 bhi = __ldg((const float4*)(bp + 4));
#pragma unroll
        for (int r = 0; r < 8; r++) {
            float2 v0 = unpack2(acc[r][0]), v1 = unpack2(acc[r][1]);
            float2 v2 = unpack2(acc[r][2]), v3 = unpack2(acc[r][3]);
            float4 a = make_float4(fmaxf(v0.x + blo.x, 0.f), fmaxf(v0.y + blo.y, 0.f),
                                   fmaxf(v1.x + blo.z, 0.f), fmaxf(v1.y + blo.w, 0.f));
            float4 b = make_float4(fmaxf(v2.x + bhi.x, 0.f), fmaxf(v2.y + bhi.y, 0.f),
                                   fmaxf(v3.x + bhi.z, 0.f), fmaxf(v3.y + bhi.w, 0.f));
            *(float4*)(sH + (trow * 8 + r) * 256 + c0)     = a;
            *(float4*)(sH + (trow * 8 + r) * 256 + c0 + 4) = b;
        }
    }

    // ---- stage GEMM2 weights chunk 0 (sW reads for GEMM1 finished at last sync) ----
#pragma unroll
    for (int i = 0; i < 4; i++) {
        int u = tid + 256 * i;
        int r = u >> 6;
        int c = (u & 63) * 4;
        const float* base = (c < 128) ? (W2l + c) : (A2l + (c - 128));
        wp[i] = base + r * 128;
    }
#pragma unroll
    for (int i = 0; i < 4; i++) { pf[i] = __ldg((const float4*)wp[i]); wp[i] += KB * 128; }
#pragma unroll
    for (int i = 0; i < 4; i++) *(float4*)(sW + (tid + 256 * i) * 4) = pf[i];
    __syncthreads();

#pragma unroll
    for (int r = 0; r < 8; r++)
#pragma unroll
        for (int p = 0; p < 4; p++) acc[r][p] = 0ull;

    const int koff = (tcol < 16) ? 0 : 128;   // msg half uses H1, att half uses H2

    // ---- GEMM2: K = 128 (8 chunks of 16) ----
#pragma unroll 1
    for (int ch = 0; ch < 8; ch++) {
        if (ch < 7) {
#pragma unroll
            for (int i = 0; i < 4; i++) { pf[i] = __ldg((const float4*)wp[i]); wp[i] += KB * 128; }
        }
        const int kbase = koff + ch * KB;
#pragma unroll
        for (int kq = 0; kq < 4; kq++) {
            float4 xr[8];
#pragma unroll
            for (int r = 0; r < 8; r++)
                xr[r] = *(const float4*)(sH + (trow * 8 + r) * 256 + kbase + kq * 4);
#pragma unroll
            for (int kk = 0; kk < 4; kk++) {
                const float* wr = sW + (kq * 4 + kk) * 256 + c0;
                ulonglong2 wa = *(const ulonglong2*)wr;
                ulonglong2 wb = *(const ulonglong2*)(wr + 4);
#pragma unroll
                for (int r = 0; r < 8; r++) {
                    float x = (kk == 0) ? xr[r].x : (kk == 1) ? xr[r].y : (kk == 2) ? xr[r].z : xr[r].w;
                    u64 xx = pack2(x, x);
                    fma2(acc[r][0], xx, wa.x);
                    fma2(acc[r][1], xx, wa.y);
                    fma2(acc[r][2], xx, wb.x);
                    fma2(acc[r][3], xx, wb.y);
                }
            }
        }
        __syncthreads();
        if (ch < 7) {
#pragma unroll
            for (int i = 0; i < 4; i++) *(float4*)(sW + (tid + 256 * i) * 4) = pf[i];
            __syncthreads();
        }
    }

    // ---- store raw OUT into sH (all GEMM2 reads done at last sync) ----
#pragma unroll
    for (int r = 0; r < 8; r++) {
        float2 v0 = unpack2(acc[r][0]), v1 = unpack2(acc[r][1]);
        float2 v2 = unpack2(acc[r][2]), v3 = unpack2(acc[r][3]);
        *(float4*)(sH + (trow * 8 + r) * 256 + c0)     = make_float4(v0.x, v0.y, v1.x, v1.y);
        *(float4*)(sH + (trow * 8 + r) * 256 + c0 + 4) = make_float4(v2.x, v2.y, v3.x, v3.y);
    }
    __syncthreads();

    // ---- gate + scatter-add ----
    {
        const int n  = tid & 127;
        const int mb = tid >> 7;
        const float b2v  = __ldg(b2l + n);
        const float ab2v = __ldg(ab2l + n);
#pragma unroll
        for (int i = 0; i < 32; i++) {
            int m = mb + 2 * i;
            float msg = sH[m * 256 + n] + b2v;
            float att = sH[m * 256 + 128 + n] + ab2v;
            float v = msg * sigmoidf_(att);
            atomicAdd(g_accum + sDst[m] * DDIM + n, v);
        }
    }
}

// ---------------- fused GRU kernel -------------------------------------------
// Per CTA: 32 nodes. G[32,512] = [msg|h] @ Wg, then gate math -> g_state.
__global__ void __launch_bounds__(256) gru_kernel(int layer)
{
    extern __shared__ float sm[];
    float* sA = sm;                  // 32 x 256 : [msg | h]
    float* sW = sA + GB * 256;       // 8 x 512
    float* sG = sW + GKB * 512;      // 32 x 512

    const int tid = threadIdx.x;
    const int m0  = blockIdx.x * GB;

    // stage A
#pragma unroll
    for (int i = 0; i < 8; i++) {
        int u = tid + 256 * i;
        int r = u >> 6;
        int c = (u & 63) * 4;
        const float* src = (c < 128) ? (g_accum + (m0 + r) * DDIM + c)
                                     : (g_state + (m0 + r) * DDIM + (c - 128));
        *(float4*)(sA + u * 4) = *(const float4*)src;
    }

    const float* Wg = g_Wg + layer * 256 * 512;
    const float* wp[4];
#pragma unroll
    for (int i = 0; i < 4; i++) {
        int u = tid + 256 * i;
        int r = u >> 7;
        int c = (u & 127) * 4;
        wp[i] = Wg + r * 512 + c;
    }
    float4 pf[4];
#pragma unroll
    for (int i = 0; i < 4; i++) { pf[i] = __ldg((const float4*)wp[i]); wp[i] += GKB * 512; }
#pragma unroll
    for (int i = 0; i < 4; i++) *(float4*)(sW + (tid + 256 * i) * 4) = pf[i];
    __syncthreads();

    const int trow = tid >> 5;
    const int tcol = tid & 31;
    const int r0 = trow * 4;        // 8 groups x 4 rows
    const int c0 = tcol * 16;       // 32 groups x 16 cols

    u64 acc[4][8];
#pragma unroll
    for (int r = 0; r < 4; r++)
#pragma unroll
        for (int p = 0; p < 8; p++) acc[r][p] = 0ull;

#pragma unroll 1
    for (int ch = 0; ch < 32; ch++) {
        if (ch < 31) {
#pragma unroll
            for (int i = 0; i < 4; i++) { pf[i] = __ldg((const float4*)wp[i]); wp[i] += GKB * 512; }
        }
        const int kbase = ch * GKB;
#pragma unroll
        for (int kq = 0; kq < 2; kq++) {
            float4 xr[4];
#pragma unroll
            for (int r = 0; r < 4; r++)
                xr[r] = *(const float4*)(sA + (r0 + r) * 256 + kbase + kq * 4);
#pragma unroll
            for (int kk = 0; kk < 4; kk++) {
                const float* wr = sW + (kq * 4 + kk) * 512 + c0;
                ulonglong2 wa = *(const ulonglong2*)wr;
                ulonglong2 wb = *(const ulonglong2*)(wr + 4);
                ulonglong2 wc = *(const ulonglong2*)(wr + 8);
                ulonglong2 wd = *(const ulonglong2*)(wr + 12);
#pragma unroll
                for (int r = 0; r < 4; r++) {
                    float x = (kk == 0) ? xr[r].x : (kk == 1) ? xr[r].y : (kk == 2) ? xr[r].z : xr[r].w;
                    u64 xx = pack2(x, x);
                    fma2(acc[r][0], xx, wa.x);
                    fma2(acc[r][1], xx, wa.y);
                    fma2(acc[r][2], xx, wb.x);
                    fma2(acc[r][3], xx, wb.y);
                    fma2(acc[r][4], xx, wc.x);
                    fma2(acc[r][5], xx, wc.y);
                    fma2(acc[r][6], xx, wd.x);
                    fma2(acc[r][7], xx, wd.y);
                }
            }
        }
        __syncthreads();
        if (ch < 31) {
#pragma unroll
            for (int i = 0; i < 4; i++) *(float4*)(sW + (tid + 256 * i) * 4) = pf[i];
            __syncthreads();
        }
    }

    // store G -> sG
#pragma unroll
    for (int r = 0; r < 4; r++) {
#pragma unroll
        for (int p = 0; p < 4; p++) {
            float2 va = unpack2(acc[r][2 * p]);
            float2 vb = unpack2(acc[r][2 * p + 1]);
            *(float4*)(sG + (r0 + r) * 512 + c0 + p * 4) = make_float4(va.x, va.y, vb.x, vb.y);
        }
    }
    __syncthreads();

    // gate epilogue
    {
        const float* bg = g_bg + layer * 512;
        const int n  = tid & 127;
        const int mb = tid >> 7;
        const float br = __ldg(bg + n);
        const float bz = __ldg(bg + 128 + n);
        const float bi = __ldg(bg + 256 + n);
        const float bh = __ldg(bg + 384 + n);
#pragma unroll
        for (int i = 0; i < 16; i++) {
            int m = mb + 2 * i;
            float r  = sigmoidf_(sG[m * 512 + n] + br);
            float z  = sigmoidf_(sG[m * 512 + 128 + n] + bz);
            float nn = tanhf_(sG[m * 512 + 256 + n] + bi + r * (sG[m * 512 + 384 + n] + bh));
            float h  = sA[m * 256 + 128 + n];
            if (m0 + m < NN)
                g_state[(m0 + m) * DDIM + n] = (1.f - z) * nn + z * h;
        }
    }
}

// ---------------- host entry --------------------------------------------------
extern "C" void kernel_launch(void* const* d_in, const int* in_sizes, int n_in,
                              void* d_out, int out_size)
{
    const float* node_feat = (const float*)d_in[0];
    const int*   ei   = (const int*)d_in[1];
    const float* ef   = (const float*)d_in[2];
    const float* W1   = (const float*)d_in[3];
    const float* b1   = (const float*)d_in[4];
    const float* W2   = (const float*)d_in[5];
    const float* b2   = (const float*)d_in[6];
    const float* A1   = (const float*)d_in[7];
    const float* ab1  = (const float*)d_in[8];
    const float* A2   = (const float*)d_in[9];
    const float* ab2  = (const float*)d_in[10];
    const float* Wih  = (const float*)d_in[11];
    const float* bih  = (const float*)d_in[12];
    const float* Whh  = (const float*)d_in[13];
    const float* bhh  = (const float*)d_in[14];

    cudaFuncSetAttribute(edge_kernel, cudaFuncAttributeMaxDynamicSharedMemorySize, EDGE_SMEM);
    cudaFuncSetAttribute(gru_kernel,  cudaFuncAttributeMaxDynamicSharedMemorySize, GRU_SMEM);

    copyin_kernel<<<(NN * DDIM / 4 + 255) / 256, 256>>>(node_feat);
    prep_kernel<<<(NLAYERS * 256 * 512 + 255) / 256, 256>>>(Wih, bih, Whh, bhh);

    for (int l = 0; l < NLAYERS; l++) {
        if (l > 0) relu_kernel<<<(NN * DDIM / 4 + 255) / 256, 256>>>();
        for (int p = 0; p < 2; p++) {
            zero_accum_kernel<<<(NPAD * DDIM / 4 + 255) / 256, 256>>>();
            edge_kernel<<<MM / BM, 256, EDGE_SMEM>>>(
                ei, ef,
                W1 + l * KIN * DDIM, b1 + l * DDIM,
                W2 + l * DDIM * DDIM, b2 + l * DDIM,
                A1 + l * KIN * DDIM, ab1 + l * DDIM,
                A2 + l * DDIM * DDIM, ab2 + l * DDIM);
            gru_kernel<<<NPAD / GB, 256, GRU_SMEM>>>(l);
        }
    }
    copyout_kernel<<<(NN * DDIM / 4 + 255) / 256, 256>>>((float*)d_out);
}

// round 14
// speedup vs baseline: 1.0023x; 1.0023x over previous
#include <cuda_runtime.h>

#define NN     50000
#define NPAD   50016
#define MM     800000
#define DDIM   128
#define EDIM   32
#define KIN    160          // D + E
#define NLAYERS 2

#define BM   64             // edges per CTA (edge kernel)
#define KB   16             // K-chunk (edge kernel)
#define GB   32             // nodes per CTA (gru kernel)
#define GKB  8              // K-chunk (gru kernel)

#define EDGE_SMEM ((BM*KIN + BM*256 + KB*256 + BM) * 4)
#define GRU_SMEM  ((GB*256 + GKB*512 + GB*512) * 4)

typedef unsigned long long u64;

// ---------------- device scratch (globals: allocation-free rule) -------------
__device__ float g_state[NPAD * DDIM];          // 25.6 MB
__device__ float g_accum[NPAD * DDIM];          // 25.6 MB
__device__ float g_Wg[NLAYERS * 256 * 512];     // packed GRU weights
__device__ float g_bg[NLAYERS * 512];           // packed GRU biases

// ---------------- f32x2 helpers ----------------------------------------------
__device__ __forceinline__ u64 pack2(float x, float y) {
    u64 r; asm("mov.b64 %0, {%1,%2};" : "=l"(r) : "f"(x), "f"(y)); return r;
}
__device__ __forceinline__ void fma2(u64& d, u64 a, u64 b) {
    asm("fma.rn.f32x2 %0, %1, %2, %0;" : "+l"(d) : "l"(a), "l"(b));
}
__device__ __forceinline__ float2 unpack2(u64 v) {
    float lo, hi; asm("mov.b64 {%0,%1}, %2;" : "=f"(lo), "=f"(hi) : "l"(v));
    return make_float2(lo, hi);
}
__device__ __forceinline__ float sigmoidf_(float x) {
    return __fdividef(1.f, 1.f + __expf(-x));
}
__device__ __forceinline__ float tanhf_(float x) {
    // 1 - 2/(e^{2x}+1); saturates correctly at +-inf
    return 1.f - __fdividef(2.f, __expf(2.f * x) + 1.f);
}

// ---------------- small utility kernels --------------------------------------
__global__ void copyin_kernel(const float* __restrict__ nf) {
    int i = blockIdx.x * blockDim.x + threadIdx.x;
    if (i < NN * DDIM / 4) ((float4*)g_state)[i] = ((const float4*)nf)[i];
}
__global__ void copyout_kernel(float* __restrict__ out) {
    int i = blockIdx.x * blockDim.x + threadIdx.x;
    if (i < NN * DDIM / 4) ((float4*)out)[i] = ((const float4*)g_state)[i];
}
__global__ void zero_accum_kernel() {
    int i = blockIdx.x * blockDim.x + threadIdx.x;
    if (i < NPAD * DDIM / 4) ((float4*)g_accum)[i] = make_float4(0.f, 0.f, 0.f, 0.f);
}
__global__ void relu_kernel() {
    int i = blockIdx.x * blockDim.x + threadIdx.x;
    if (i < NN * DDIM / 4) {
        float4 v = ((float4*)g_state)[i];
        v.x = fmaxf(v.x, 0.f); v.y = fmaxf(v.y, 0.f);
        v.z = fmaxf(v.z, 0.f); v.w = fmaxf(v.w, 0.f);
        ((float4*)g_state)[i] = v;
    }
}

// Pack GRU weights: Wg[l][k][c], k in [0,256) = [msg | h] rows,
// c sections: [0,128)=r (Wih+Whh), [128,256)=z, [256,384)=gin (Wih only),
// [384,512)=ghn (Whh only).
__global__ void prep_kernel(const float* __restrict__ Wih, const float* __restrict__ bih,
                            const float* __restrict__ Whh, const float* __restrict__ bhh) {
    int idx = blockIdx.x * blockDim.x + threadIdx.x;
    if (idx < NLAYERS * 256 * 512) {
        int l = idx / (256 * 512);
        int rr = idx % (256 * 512);
        int k = rr / 512;
        int c = rr % 512;
        const float* wih = Wih + l * 128 * 384;
        const float* whh = Whh + l * 128 * 384;
        float v;
        if (c < 256) {                       // r,z: original col = c
            v = (k < 128) ? wih[k * 384 + c] : whh[(k - 128) * 384 + c];
        } else if (c < 384) {                // gin: original col = c
            v = (k < 128) ? wih[k * 384 + c] : 0.f;
        } else {                             // ghn: original col = c-128
            v = (k < 128) ? 0.f : whh[(k - 128) * 384 + (c - 128)];
        }
        g_Wg[idx] = v;
    }
    if (idx < NLAYERS * 512) {
        int l = idx / 512, c = idx % 512;
        const float* bi = bih + l * 384;
        const float* bh = bhh + l * 384;
        float v;
        if (c < 256)      v = bi[c] + bh[c];
        else if (c < 384) v = bi[c];
        else              v = bh[c - 128];
        g_bg[idx] = v;
    }
}

// ---------------- fused edge kernel ------------------------------------------
// Per CTA: 64 edges. X[64,160] -> H[64,256]=relu(X@[W1|A1]+[b1|ab1])
// -> OUT[64,256]=[H1@W2 | H2@A2] -> msg*(sigmoid(att)) -> RED.ADD into g_accum.
__global__ void __launch_bounds__(256) edge_kernel(
    const int*   __restrict__ ei,  const float* __restrict__ ef,
    const float* __restrict__ W1l, const float* __restrict__ b1l,
    const float* __restrict__ W2l, const float* __restrict__ b2l,
    const float* __restrict__ A1l, const float* __restrict__ ab1l,
    const float* __restrict__ A2l, const float* __restrict__ ab2l)
{
    extern __shared__ float sm[];
    float* sX = sm;                       // 64 x 160
    float* sH = sX + BM * KIN;            // 64 x 256 (later reused as OUT)
    float* sW = sH + BM * 256;            // 16 x 256
    int*   sDst = (int*)(sW + KB * 256);  // 64

    const int tid  = threadIdx.x;
    const int e0   = blockIdx.x * BM;
    const int w    = tid >> 5;
    const int lane = tid & 31;

    // ---- gather X = [state[src]-state[dst] | edge_feat] ----
#pragma unroll
    for (int j = 0; j < 8; j++) {
        int m   = w * 8 + j;
        int src = __ldg(ei + e0 + m);
        int dst = __ldg(ei + MM + e0 + m);
        if (lane == 0) sDst[m] = dst;
        float4 s4 = *(const float4*)(g_state + src * DDIM + lane * 4);
        float4 d4 = *(const float4*)(g_state + dst * DDIM + lane * 4);
        float4 x  = make_float4(s4.x - d4.x, s4.y - d4.y, s4.z - d4.z, s4.w - d4.w);
        *(float4*)(sX + m * KIN + lane * 4) = x;
        if (lane < 8)
            *(float4*)(sX + m * KIN + 128 + lane * 4) =
                *(const float4*)(ef + (e0 + m) * EDIM + lane * 4);
    }

    const int trow = tid >> 5;     // 8 row groups x 8 rows
    const int tcol = tid & 31;     // 32 col groups x 8 cols
    const int c0   = tcol * 8;

    // ---- prefetch setup for GEMM1 weights [W1 | A1], rows = K ----
    const float* wp[4];
#pragma unroll
    for (int i = 0; i < 4; i++) {
        int u = tid + 256 * i;
        int r = u >> 6;
        int c = (u & 63) * 4;
        const float* base = (c < 128) ? (W1l + c) : (A1l + (c - 128));
        wp[i] = base + r * 128;
    }
    float4 pf[4];
#pragma unroll
    for (int i = 0; i < 4; i++) { pf[i] = __ldg((const float4*)wp[i]); wp[i] += KB * 128; }
#pragma unroll
    for (int i = 0; i < 4; i++) *(float4*)(sW + (tid + 256 * i) * 4) = pf[i];
    __syncthreads();

    u64 acc[8][4];
#pragma unroll
    for (int r = 0; r < 8; r++)
#pragma unroll
        for (int p = 0; p < 4; p++) acc[r][p] = 0ull;

    // ---- GEMM1: K = 160 (10 chunks of 16) ----
#pragma unroll 1
    for (int ch = 0; ch < 10; ch++) {
        if (ch < 9) {
#pragma unroll
            for (int i = 0; i < 4; i++) { pf[i] = __ldg((const float4*)wp[i]); wp[i] += KB * 128; }
        }
        const int kbase = ch * KB;
#pragma unroll
        for (int kq = 0; kq < 4; kq++) {
            float4 xr[8];
#pragma unroll
            for (int r = 0; r < 8; r++)
                xr[r] = *(const float4*)(sX + (trow * 8 + r) * KIN + kbase + kq * 4);
#pragma unroll
            for (int kk = 0; kk < 4; kk++) {
                const float* wr = sW + (kq * 4 + kk) * 256 + c0;
                ulonglong2 wa = *(const ulonglong2*)wr;
                ulonglong2 wb = *(const ulonglong2*)(wr + 4);
#pragma unroll
                for (int r = 0; r < 8; r++) {
                    float x = (kk == 0) ? xr[r].x : (kk == 1) ? xr[r].y : (kk == 2) ? xr[r].z : xr[r].w;
                    u64 xx = pack2(x, x);
                    fma2(acc[r][0], xx, wa.x);
                    fma2(acc[r][1], xx, wa.y);
                    fma2(acc[r][2], xx, wb.x);
                    fma2(acc[r][3], xx, wb.y);
                }
            }
        }
        __syncthreads();
        if (ch < 9) {
#pragma unroll
            for (int i = 0; i < 4; i++) *(float4*)(sW + (tid + 256 * i) * 4) = pf[i];
            __syncthreads();
        }
    }

    // ---- GEMM1 epilogue: bias + relu -> sH ----
    {
        const float* bp = (tcol < 16) ? (b1l + c0) : (ab1l + (c0 - 128));
        float4 blo = __ldg((const float4*)bp);
        float4 bhi = __ldg((const float4*)(bp + 4));
#pragma unroll
        for (int r = 0; r < 8; r++) {
            float2 v0 = unpack2(acc[r][0]), v1 = unpack2(acc[r][1]);
            float2 v2 = unpack2(acc[r][2]), v3 = unpack2(acc[r][3]);
            float4 a = make_float4(fmaxf(v0.x + blo.x, 0.f), fmaxf(v0.y + blo.y, 0.f),
                                   fmaxf(v1.x + blo.z, 0.f), fmaxf(v1.y + blo.w, 0.f));
            float4 b = make_float4(fmaxf(v2.x + bhi.x, 0.f), fmaxf(v2.y + bhi.y, 0.f),
                                   fmaxf(v3.x + bhi.z, 0.f), fmaxf(v3.y + bhi.w, 0.f));
            *(float4*)(sH + (trow * 8 + r) * 256 + c0)     = a;
            *(float4*)(sH + (trow * 8 + r) * 256 + c0 + 4) = b;
        }
    }

    // ---- stage GEMM2 weights chunk 0 (sW reads for GEMM1 finished at last sync) ----
#pragma unroll
    for (int i = 0; i < 4; i++) {
        int u = tid + 256 * i;
        int r = u >> 6;
        int c = (u & 63) * 4;
        const float* base = (c < 128) ? (W2l + c) : (A2l + (c - 128));
        wp[i] = base + r * 128;
    }
#pragma unroll
    for (int i = 0; i < 4; i++) { pf[i] = __ldg((const float4*)wp[i]); wp[i] += KB * 128; }
#pragma unroll
    for (int i = 0; i < 4; i++) *(float4*)(sW + (tid + 256 * i) * 4) = pf[i];
    __syncthreads();

#pragma unroll
    for (int r = 0; r < 8; r++)
#pragma unroll
        for (int p = 0; p < 4; p++) acc[r][p] = 0ull;

    const int koff = (tcol < 16) ? 0 : 128;   // msg half uses H1, att half uses H2

    // ---- GEMM2: K = 128 (8 chunks of 16) ----
#pragma unroll 1
    for (int ch = 0; ch < 8; ch++) {
        if (ch < 7) {
#pragma unroll
            for (int i = 0; i < 4; i++) { pf[i] = __ldg((const float4*)wp[i]); wp[i] += KB * 128; }
        }
        const int kbase = koff + ch * KB;
#pragma unroll
        for (int kq = 0; kq < 4; kq++) {
            float4 xr[8];
#pragma unroll
            for (int r = 0; r < 8; r++)
                xr[r] = *(const float4*)(sH + (trow * 8 + r) * 256 + kbase + kq * 4);
#pragma unroll
            for (int kk = 0; kk < 4; kk++) {
                const float* wr = sW + (kq * 4 + kk) * 256 + c0;
                ulonglong2 wa = *(const ulonglong2*)wr;
                ulonglong2 wb = *(const ulonglong2*)(wr + 4);
#pragma unroll
                for (int r = 0; r < 8; r++) {
                    float x = (kk == 0) ? xr[r].x : (kk == 1) ? xr[r].y : (kk == 2) ? xr[r].z : xr[r].w;
                    u64 xx = pack2(x, x);
                    fma2(acc[r][0], xx, wa.x);
                    fma2(acc[r][1], xx, wa.y);
                    fma2(acc[r][2], xx, wb.x);
                    fma2(acc[r][3], xx, wb.y);
                }
            }
        }
        __syncthreads();
        if (ch < 7) {
#pragma unroll
            for (int i = 0; i < 4; i++) *(float4*)(sW + (tid + 256 * i) * 4) = pf[i];
            __syncthreads();
        }
    }

    // ---- store raw OUT into sH (all GEMM2 reads done at last sync) ----
#pragma unroll
    for (int r = 0; r < 8; r++) {
        float2 v0 = unpack2(acc[r][0]), v1 = unpack2(acc[r][1]);
        float2 v2 = unpack2(acc[r][2]), v3 = unpack2(acc[r][3]);
        *(float4*)(sH + (trow * 8 + r) * 256 + c0)     = make_float4(v0.x, v0.y, v1.x, v1.y);
        *(float4*)(sH + (trow * 8 + r) * 256 + c0 + 4) = make_float4(v2.x, v2.y, v3.x, v3.y);
    }
    __syncthreads();

    // ---- gate + scatter-add ----
    {
        const int n  = tid & 127;
        const int mb = tid >> 7;
        const float b2v  = __ldg(b2l + n);
        const float ab2v = __ldg(ab2l + n);
#pragma unroll
        for (int i = 0; i < 32; i++) {
            int m = mb + 2 * i;
            float msg = sH[m * 256 + n] + b2v;
            float att = sH[m * 256 + 128 + n] + ab2v;
            float v = msg * sigmoidf_(att);
            atomicAdd(g_accum + sDst[m] * DDIM + n, v);
        }
    }
}

// ---------------- fused GRU kernel -------------------------------------------
// Per CTA: 32 nodes. G[32,512] = [msg|h] @ Wg, then gate math -> g_state.
__global__ void __launch_bounds__(256) gru_kernel(int layer)
{
    extern __shared__ float sm[];
    float* sA = sm;                  // 32 x 256 : [msg | h]
    float* sW = sA + GB * 256;       // 8 x 512
    float* sG = sW + GKB * 512;      // 32 x 512

    const int tid = threadIdx.x;
    const int m0  = blockIdx.x * GB;

    // stage A
#pragma unroll
    for (int i = 0; i < 8; i++) {
        int u = tid + 256 * i;
        int r = u >> 6;
        int c = (u & 63) * 4;
        const float* src = (c < 128) ? (g_accum + (m0 + r) * DDIM + c)
                                     : (g_state + (m0 + r) * DDIM + (c - 128));
        *(float4*)(sA + u * 4) = *(const float4*)src;
    }

    const float* Wg = g_Wg + layer * 256 * 512;
    const float* wp[4];
#pragma unroll
    for (int i = 0; i < 4; i++) {
        int u = tid + 256 * i;
        int r = u >> 7;
        int c = (u & 127) * 4;
        wp[i] = Wg + r * 512 + c;
    }
    float4 pf[4];
#pragma unroll
    for (int i = 0; i < 4; i++) { pf[i] = __ldg((const float4*)wp[i]); wp[i] += GKB * 512; }
#pragma unroll
    for (int i = 0; i < 4; i++) *(float4*)(sW + (tid + 256 * i) * 4) = pf[i];
    __syncthreads();

    const int trow = tid >> 5;
    const int tcol = tid & 31;
    const int r0 = trow * 4;        // 8 groups x 4 rows
    const int c0 = tcol * 16;       // 32 groups x 16 cols

    u64 acc[4][8];
#pragma unroll
    for (int r = 0; r < 4; r++)
#pragma unroll
        for (int p = 0; p < 8; p++) acc[r][p] = 0ull;

#pragma unroll 1
    for (int ch = 0; ch < 32; ch++) {
        if (ch < 31) {
#pragma unroll
            for (int i = 0; i < 4; i++) { pf[i] = __ldg((const float4*)wp[i]); wp[i] += GKB * 512; }
        }
        const int kbase = ch * GKB;
#pragma unroll
        for (int kq = 0; kq < 2; kq++) {
            float4 xr[4];
#pragma unroll
            for (int r = 0; r < 4; r++)
                xr[r] = *(const float4*)(sA + (r0 + r) * 256 + kbase + kq * 4);
#pragma unroll
            for (int kk = 0; kk < 4; kk++) {
                const float* wr = sW + (kq * 4 + kk) * 512 + c0;
                ulonglong2 wa = *(const ulonglong2*)wr;
                ulonglong2 wb = *(const ulonglong2*)(wr + 4);
                ulonglong2 wc = *(const ulonglong2*)(wr + 8);
                ulonglong2 wd = *(const ulonglong2*)(wr + 12);
#pragma unroll
                for (int r = 0; r < 4; r++) {
                    float x = (kk == 0) ? xr[r].x : (kk == 1) ? xr[r].y : (kk == 2) ? xr[r].z : xr[r].w;
                    u64 xx = pack2(x, x);
                    fma2(acc[r][0], xx, wa.x);
                    fma2(acc[r][1], xx, wa.y);
                    fma2(acc[r][2], xx, wb.x);
                    fma2(acc[r][3], xx, wb.y);
                    fma2(acc[r][4], xx, wc.x);
                    fma2(acc[r][5], xx, wc.y);
                    fma2(acc[r][6], xx, wd.x);
                    fma2(acc[r][7], xx, wd.y);
                }
            }
        }
        __syncthreads();
        if (ch < 31) {
#pragma unroll
            for (int i = 0; i < 4; i++) *(float4*)(sW + (tid + 256 * i) * 4) = pf[i];
            __syncthreads();
        }
    }

    // store G -> sG
#pragma unroll
    for (int r = 0; r < 4; r++) {
#pragma unroll
        for (int p = 0; p < 4; p++) {
            float2 va = unpack2(acc[r][2 * p]);
            float2 vb = unpack2(acc[r][2 * p + 1]);
            *(float4*)(sG + (r0 + r) * 512 + c0 + p * 4) = make_float4(va.x, va.y, vb.x, vb.y);
        }
    }
    __syncthreads();

    // gate epilogue
    {
        const float* bg = g_bg + layer * 512;
        const int n  = tid & 127;
        const int mb = tid >> 7;
        const float br = __ldg(bg + n);
        const float bz = __ldg(bg + 128 + n);
        const float bi = __ldg(bg + 256 + n);
        const float bh = __ldg(bg + 384 + n);
#pragma unroll
        for (int i = 0; i < 16; i++) {
            int m = mb + 2 * i;
            float r  = sigmoidf_(sG[m * 512 + n] + br);
            float z  = sigmoidf_(sG[m * 512 + 128 + n] + bz);
            float nn = tanhf_(sG[m * 512 + 256 + n] + bi + r * (sG[m * 512 + 384 + n] + bh));
            float h  = sA[m * 256 + 128 + n];
            if (m0 + m < NN)
                g_state[(m0 + m) * DDIM + n] = (1.f - z) * nn + z * h;
        }
    }
}

// ---------------- host entry --------------------------------------------------
extern "C" void kernel_launch(void* const* d_in, const int* in_sizes, int n_in,
                              void* d_out, int out_size)
{
    const float* node_feat = (const float*)d_in[0];
    const int*   ei   = (const int*)d_in[1];
    const float* ef   = (const float*)d_in[2];
    const float* W1   = (const float*)d_in[3];
    const float* b1   = (const float*)d_in[4];
    const float* W2   = (const float*)d_in[5];
    const float* b2   = (const float*)d_in[6];
    const float* A1   = (const float*)d_in[7];
    const float* ab1  = (const float*)d_in[8];
    const float* A2   = (const float*)d_in[9];
    const float* ab2  = (const float*)d_in[10];
    const float* Wih  = (const float*)d_in[11];
    const float* bih  = (const float*)d_in[12];
    const float* Whh  = (const float*)d_in[13];
    const float* bhh  = (const float*)d_in[14];

    cudaFuncSetAttribute(edge_kernel, cudaFuncAttributeMaxDynamicSharedMemorySize, EDGE_SMEM);
    cudaFuncSetAttribute(gru_kernel,  cudaFuncAttributeMaxDynamicSharedMemorySize, GRU_SMEM);

    copyin_kernel<<<(NN * DDIM / 4 + 255) / 256, 256>>>(node_feat);
    prep_kernel<<<(NLAYERS * 256 * 512 + 255) / 256, 256>>>(Wih, bih, Whh, bhh);

    for (int l = 0; l < NLAYERS; l++) {
        if (l > 0) relu_kernel<<<(NN * DDIM / 4 + 255) / 256, 256>>>();
        for (int p = 0; p < 2; p++) {
            zero_accum_kernel<<<(NPAD * DDIM / 4 + 255) / 256, 256>>>();
            edge_kernel<<<MM / BM, 256, EDGE_SMEM>>>(
                ei, ef,
                W1 + l * KIN * DDIM, b1 + l * DDIM,
                W2 + l * DDIM * DDIM, b2 + l * DDIM,
                A1 + l * KIN * DDIM, ab1 + l * DDIM,
                A2 + l * DDIM * DDIM, ab2 + l * DDIM);
            gru_kernel<<<NPAD / GB, 256, GRU_SMEM>>>(l);
        }
    }
    copyout_kernel<<<(NN * DDIM / 4 + 255) / 256, 256>>>((float*)d_out);
}